// round 1
// baseline (speedup 1.0000x reference)
#include <cuda_runtime.h>
#include <cstdint>

// Problem constants
#define BATCH 4
#define NPTS 8192
#define KNN 16
#define NP_TOTAL (BATCH * NPTS)   // 32768

// conv1: Cin3 = 259 (xyz+256), stride 260, F = 2072, Cout = 128
// conv2: Cin3 = 131 (xyz+128), stride 132, F = 1048, Cout = 128

// ---------------- scratch (static device globals; allocation-free) -----------
__device__ float g_fcat1[NP_TOTAL * 260];   // point-major [p][260] (xyz + feat256)
__device__ float g_fcat2[NP_TOTAL * 132];   // point-major [p][132] (xyz + conv1 out)
__device__ float g_f2[NP_TOTAL * 128];      // conv2 out, point-major
__device__ float g_Lt1[2072 * 128];         // w_lin1 transposed: [f][o]
__device__ float g_Lt2[1048 * 128];         // w_lin2 transposed: [f][o]
__device__ float g_w1t[128 * 128];          // w_mlp1 transposed: [c][o]
__device__ float g_w2t[128 * 64];           // w_mlp2 transposed: [o][j]

__device__ __forceinline__ float leaky(float v) { return v >= 0.f ? v : 0.1f * v; }

// ---------------- prep kernels ------------------------------------------------
__global__ void prep_weights(const float* __restrict__ wl1, const float* __restrict__ wl2,
                             const float* __restrict__ wm1, const float* __restrict__ wm2) {
    int i = blockIdx.x * blockDim.x + threadIdx.x;
    if (i < 2072 * 128) { int f = i >> 7, o = i & 127; g_Lt1[i] = wl1[o * 2072 + f]; }
    if (i < 1048 * 128) { int f = i >> 7, o = i & 127; g_Lt2[i] = wl2[o * 1048 + f]; }
    if (i < 128 * 128)  { int c = i >> 7, o = i & 127; g_w1t[i] = wm1[o * 128 + c]; }
    if (i < 128 * 64)   { int o = i >> 6, j = i & 63;  g_w2t[i] = wm2[j * 128 + o]; }
}

__global__ void prep_xyz(const float* __restrict__ xyz) {
    int i = blockIdx.x * blockDim.x + threadIdx.x;
    if (i >= NP_TOTAL * 3) return;
    int p = i / 3, d = i - p * 3;
    int b = p >> 13, n = p & (NPTS - 1);
    float v = xyz[((size_t)b * 3 + d) * NPTS + n];
    g_fcat1[(size_t)p * 260 + d] = v;
    g_fcat2[(size_t)p * 132 + d] = v;
}

// feat [B,256,N] -> g_fcat1[p][3 + c]  (32x32 smem tile transpose)
__global__ void transpose_feat(const float* __restrict__ feat) {
    __shared__ float tile[32][33];
    int b = blockIdx.z;
    int n0 = blockIdx.x * 32, c0 = blockIdx.y * 32;
    int x = threadIdx.x, y = threadIdx.y;
    tile[y][x] = feat[((size_t)b * 256 + c0 + y) * NPTS + n0 + x];
    __syncthreads();
    g_fcat1[((size_t)(b * NPTS + n0 + y)) * 260 + 3 + c0 + x] = tile[x][y];
}

// ---------------- fused point-conv ------------------------------------------
// CTA: 256 threads, 8 points. smem: agg[8][F] + w[8][16][8] + nbr[8][16]
template <int CIN3, int STRIDE_IN, int F, int OUT_STRIDE, int OUT_OFF>
__global__ void conv_kernel(const float* __restrict__ fcat, const int* __restrict__ knn,
                            const float* __restrict__ w_wn, const float* __restrict__ b_wn,
                            const float* __restrict__ Lt, const float* __restrict__ b_lin,
                            float* __restrict__ out) {
    extern __shared__ float sm[];
    float* s_agg = sm;                      // 8*F floats
    float* s_w   = sm + 8 * F;              // 1024 floats, [t][k][m]
    int*   s_nbr = (int*)(s_w + 1024);      // 128 ints

    __shared__ float s_wn[24];
    __shared__ float s_bwn[8];

    const int tid  = threadIdx.x;
    const int base = blockIdx.x * 8;

    if (tid < 24) s_wn[tid] = w_wn[tid];
    if (tid < 8)  s_bwn[tid] = b_wn[tid];

    int j = -1, t = 0, k = 0, p = 0;
    if (tid < 128) {
        t = tid >> 4; k = tid & 15; p = base + t;
        int b = p >> 13;
        j = (b << 13) + knn[(size_t)p * KNN + k];
        s_nbr[t * 16 + k] = j;
    }
    __syncthreads();

    // weight-net: w[t][k][m] = leaky(w_wn @ (xyz_j - xyz_p) + b_wn)
    if (tid < 128) {
        const float* cp = fcat + (size_t)p * STRIDE_IN;
        const float* np_ = fcat + (size_t)j * STRIDE_IN;
        float px = np_[0] - cp[0];
        float py = np_[1] - cp[1];
        float pz = np_[2] - cp[2];
#pragma unroll
        for (int m = 0; m < 8; ++m) {
            float v = s_wn[m * 3 + 0] * px + s_wn[m * 3 + 1] * py + s_wn[m * 3 + 2] * pz + s_bwn[m];
            s_w[(t * 16 + k) * 8 + m] = leaky(v);
        }
    }
    __syncthreads();

    // agg build: warp w handles point t=w
    {
        const int wt   = tid >> 5;
        const int lane = tid & 31;
        int nbr_r[16];
#pragma unroll
        for (int kk = 0; kk < 16; ++kk) nbr_r[kk] = s_nbr[wt * 16 + kk];
        const float* wp = s_w + wt * 128;
        for (int c = lane; c < CIN3; c += 32) {
            float acc[8];
#pragma unroll
            for (int m = 0; m < 8; ++m) acc[m] = 0.f;
#pragma unroll
            for (int kk = 0; kk < 16; ++kk) {
                float fv = __ldg(&fcat[(size_t)nbr_r[kk] * STRIDE_IN + c]);
                float4 w0 = *(const float4*)(wp + kk * 8);
                float4 w1 = *(const float4*)(wp + kk * 8 + 4);
                acc[0] += fv * w0.x; acc[1] += fv * w0.y;
                acc[2] += fv * w0.z; acc[3] += fv * w0.w;
                acc[4] += fv * w1.x; acc[5] += fv * w1.y;
                acc[6] += fv * w1.z; acc[7] += fv * w1.w;
            }
            float* ap = s_agg + (size_t)wt * F + c * 8;
#pragma unroll
            for (int m = 0; m < 8; ++m) ap[m] = acc[m];
        }
    }
    __syncthreads();

    // big GEMM: out[t][o] = leaky(b[o] + sum_f agg[t][f] * Lt[f][o])
    {
        const int half = tid >> 7;          // 0/1 -> points half*4 .. half*4+3
        const int o    = tid & 127;
        float acc0 = 0.f, acc1 = 0.f, acc2 = 0.f, acc3 = 0.f;
        const float* a0 = s_agg + (size_t)(half * 4 + 0) * F;
        const float* a1 = s_agg + (size_t)(half * 4 + 1) * F;
        const float* a2 = s_agg + (size_t)(half * 4 + 2) * F;
        const float* a3 = s_agg + (size_t)(half * 4 + 3) * F;
        const float* ltp = Lt + o;
        for (int f = 0; f < F; f += 4) {
            float l0 = __ldg(ltp + (size_t)(f + 0) * 128);
            float l1 = __ldg(ltp + (size_t)(f + 1) * 128);
            float l2 = __ldg(ltp + (size_t)(f + 2) * 128);
            float l3 = __ldg(ltp + (size_t)(f + 3) * 128);
            float4 v0 = *(const float4*)(a0 + f);
            float4 v1 = *(const float4*)(a1 + f);
            float4 v2 = *(const float4*)(a2 + f);
            float4 v3 = *(const float4*)(a3 + f);
            acc0 += v0.x * l0; acc0 += v0.y * l1; acc0 += v0.z * l2; acc0 += v0.w * l3;
            acc1 += v1.x * l0; acc1 += v1.y * l1; acc1 += v1.z * l2; acc1 += v1.w * l3;
            acc2 += v2.x * l0; acc2 += v2.y * l1; acc2 += v2.z * l2; acc2 += v2.w * l3;
            acc3 += v3.x * l0; acc3 += v3.y * l1; acc3 += v3.z * l2; acc3 += v3.w * l3;
        }
        float bb = b_lin[o];
        float r0 = leaky(acc0 + bb);
        float r1 = leaky(acc1 + bb);
        float r2 = leaky(acc2 + bb);
        float r3 = leaky(acc3 + bb);
        size_t ob = (size_t)(base + half * 4) * OUT_STRIDE + OUT_OFF + o;
        out[ob + 0 * OUT_STRIDE] = r0;
        out[ob + 1 * OUT_STRIDE] = r1;
        out[ob + 2 * OUT_STRIDE] = r2;
        out[ob + 3 * OUT_STRIDE] = r3;
    }
}

// ---------------- MLP head ----------------------------------------------------
// CTA: 256 threads, 16 points. h1 = leaky(W1 f + b1); h2 = leaky(W2 h1 + b2);
// flow = Wlast h2 + blast. Writes channel-major outputs.
__global__ void mlp_kernel(const float* __restrict__ w_last, const float* __restrict__ b1,
                           const float* __restrict__ b2, const float* __restrict__ blast,
                           float* __restrict__ out) {
    __shared__ float s_f[16 * 128];
    __shared__ float s_h1[16 * 128];
    __shared__ float s_h2[16 * 64];
    const int tid = threadIdx.x;
    const int p0  = blockIdx.x * 16;

    for (int i = tid; i < 16 * 128; i += 256) s_f[i] = g_f2[(size_t)p0 * 128 + i];
    __syncthreads();

    // h1: 16x128, 8 results per thread
    {
        int o = tid & 127, tg = tid >> 7;
        float acc[8];
#pragma unroll
        for (int i = 0; i < 8; ++i) acc[i] = 0.f;
        for (int c = 0; c < 128; ++c) {
            float wv = g_w1t[c * 128 + o];
#pragma unroll
            for (int i = 0; i < 8; ++i) acc[i] += s_f[(tg * 8 + i) * 128 + c] * wv;
        }
        float bb = b1[o];
#pragma unroll
        for (int i = 0; i < 8; ++i) s_h1[(tg * 8 + i) * 128 + o] = leaky(acc[i] + bb);
    }
    __syncthreads();

    // h2: 16x64, 4 results per thread
    {
        int jj = tid & 63, tg = tid >> 6;
        float acc[4];
#pragma unroll
        for (int i = 0; i < 4; ++i) acc[i] = 0.f;
        for (int c = 0; c < 128; ++c) {
            float wv = g_w2t[c * 64 + jj];
#pragma unroll
            for (int i = 0; i < 4; ++i) acc[i] += s_h1[(tg * 4 + i) * 128 + c] * wv;
        }
        float bb = b2[jj];
#pragma unroll
        for (int i = 0; i < 4; ++i) s_h2[(tg * 4 + i) * 64 + jj] = leaky(acc[i] + bb);
    }
    __syncthreads();

    const int b = p0 >> 13, n0 = p0 & (NPTS - 1);
    // flow_feat out: [B, 64, N]
    for (int i = tid; i < 16 * 64; i += 256) {
        int t = i & 15, jj = i >> 4;
        out[((size_t)(b * 64 + jj)) * NPTS + n0 + t] = s_h2[t * 64 + jj];
    }
    // flow: [B, 3, N] at offset B*64*N
    if (tid < 48) {
        int t = tid & 15, d = tid >> 4;
        float acc = 0.f;
#pragma unroll 8
        for (int jj = 0; jj < 64; ++jj) acc += w_last[d * 64 + jj] * s_h2[t * 64 + jj];
        out[(size_t)BATCH * 64 * NPTS + ((size_t)(b * 3 + d)) * NPTS + n0 + t] = acc + blast[d];
    }
}

// ---------------- launch -------------------------------------------------------
extern "C" void kernel_launch(void* const* d_in, const int* in_sizes, int n_in,
                              void* d_out, int out_size) {
    const float* xyz    = (const float*)d_in[0];
    const float* feat   = (const float*)d_in[1];
    const int*   knn    = (const int*)d_in[2];
    const float* w_wn1  = (const float*)d_in[3];
    const float* b_wn1  = (const float*)d_in[4];
    const float* w_lin1 = (const float*)d_in[5];
    const float* b_lin1 = (const float*)d_in[6];
    const float* w_wn2  = (const float*)d_in[7];
    const float* b_wn2  = (const float*)d_in[8];
    const float* w_lin2 = (const float*)d_in[9];
    const float* b_lin2 = (const float*)d_in[10];
    const float* w_mlp1 = (const float*)d_in[11];
    const float* b_mlp1 = (const float*)d_in[12];
    const float* w_mlp2 = (const float*)d_in[13];
    const float* b_mlp2 = (const float*)d_in[14];
    const float* w_last = (const float*)d_in[15];
    const float* b_last = (const float*)d_in[16];
    float* out = (float*)d_out;

    void *p_fcat1, *p_fcat2, *p_f2, *p_Lt1, *p_Lt2;
    cudaGetSymbolAddress(&p_fcat1, g_fcat1);
    cudaGetSymbolAddress(&p_fcat2, g_fcat2);
    cudaGetSymbolAddress(&p_f2, g_f2);
    cudaGetSymbolAddress(&p_Lt1, g_Lt1);
    cudaGetSymbolAddress(&p_Lt2, g_Lt2);

    // prep
    prep_weights<<<(2072 * 128 + 255) / 256, 256>>>(w_lin1, w_lin2, w_mlp1, w_mlp2);
    prep_xyz<<<(NP_TOTAL * 3 + 255) / 256, 256>>>(xyz);
    {
        dim3 tb(32, 32);
        dim3 tg(NPTS / 32, 256 / 32, BATCH);
        transpose_feat<<<tg, tb>>>(feat);
    }

    // conv1: 259 -> 128, writes g_fcat2 channels [3,131)
    {
        constexpr int F = 2072;
        size_t smem = (size_t)(8 * F + 1024) * 4 + 128 * 4;
        cudaFuncSetAttribute(conv_kernel<259, 260, F, 132, 3>,
                             cudaFuncAttributeMaxDynamicSharedMemorySize, (int)smem);
        conv_kernel<259, 260, F, 132, 3><<<NP_TOTAL / 8, 256, smem>>>(
            (const float*)p_fcat1, knn, w_wn1, b_wn1, (const float*)p_Lt1, b_lin1,
            (float*)p_fcat2);
    }
    // conv2: 131 -> 128, writes g_f2
    {
        constexpr int F = 1048;
        size_t smem = (size_t)(8 * F + 1024) * 4 + 128 * 4;
        cudaFuncSetAttribute(conv_kernel<131, 132, F, 128, 0>,
                             cudaFuncAttributeMaxDynamicSharedMemorySize, (int)smem);
        conv_kernel<131, 132, F, 128, 0><<<NP_TOTAL / 8, 256, smem>>>(
            (const float*)p_fcat2, knn, w_wn2, b_wn2, (const float*)p_Lt2, b_lin2,
            (float*)p_f2);
    }
    // mlp head + flow
    mlp_kernel<<<NP_TOTAL / 16, 256>>>(w_last, b_mlp1, b_mlp2, b_last, out);
}

// round 2
// speedup vs baseline: 1.3139x; 1.3139x over previous
#include <cuda_runtime.h>
#include <cstdint>

#define BATCH 4
#define NPTS 8192
#define KNN 16
#define NP_TOTAL (BATCH * NPTS)   // 32768

typedef unsigned long long ull;

// Layouts (point-major, feat first, xyz last):
//   g_fcat1: [p][256 feat | 3 xyz | 1 pad]  stride 260
//   g_fcat2: [p][128 feat | 3 xyz | 1 pad]  stride 132
// Lt matrices are permuted to match (xyz channels moved to the end).
__device__ float g_fcat1[NP_TOTAL * 260];
__device__ float g_fcat2[NP_TOTAL * 132];
__device__ float g_f2[NP_TOTAL * 128];
__device__ float g_Lt1[2072 * 128];
__device__ float g_Lt2[1048 * 128];
__device__ float g_w1t[128 * 128];
__device__ float g_w2t[128 * 64];

__device__ __forceinline__ float lrelu(float v) { return v >= 0.f ? v : 0.1f * v; }

__device__ __forceinline__ ull ffma2(ull a, ull b, ull c) {
    ull d;
    asm("fma.rn.f32x2 %0, %1, %2, %3;" : "=l"(d) : "l"(a), "l"(b), "l"(c));
    return d;
}
__device__ __forceinline__ ull dup2(float x) {
    ull d;
    asm("mov.b64 %0, {%1, %1};" : "=l"(d) : "f"(x));
    return d;
}
__device__ __forceinline__ float2 unpk(ull v) {
    float2 r;
    asm("mov.b64 {%0, %1}, %2;" : "=f"(r.x), "=f"(r.y) : "l"(v));
    return r;
}

// ---------------- prep kernels -----------------------------------------------
__global__ void prep_weights(const float* __restrict__ wl1, const float* __restrict__ wl2,
                             const float* __restrict__ wm1, const float* __restrict__ wm2) {
    int i = blockIdx.x * blockDim.x + threadIdx.x;
    if (i < 2072 * 128) {
        int f_new = i >> 7, o = i & 127;
        int c_new = f_new >> 3, m = f_new & 7;
        int c_orig = (c_new < 256) ? c_new + 3 : c_new - 256;
        g_Lt1[i] = wl1[o * 2072 + c_orig * 8 + m];
    }
    if (i < 1048 * 128) {
        int f_new = i >> 7, o = i & 127;
        int c_new = f_new >> 3, m = f_new & 7;
        int c_orig = (c_new < 128) ? c_new + 3 : c_new - 128;
        g_Lt2[i] = wl2[o * 1048 + c_orig * 8 + m];
    }
    if (i < 128 * 128) { int c = i >> 7, o = i & 127; g_w1t[i] = wm1[o * 128 + c]; }
    if (i < 128 * 64)  { int o = i >> 6, j = i & 63;  g_w2t[i] = wm2[j * 128 + o]; }
}

__global__ void prep_xyz(const float* __restrict__ xyz) {
    int i = blockIdx.x * blockDim.x + threadIdx.x;
    if (i >= NP_TOTAL * 3) return;
    int p = i / 3, d = i - p * 3;
    int b = p >> 13, n = p & (NPTS - 1);
    float v = xyz[((size_t)b * 3 + d) * NPTS + n];
    g_fcat1[(size_t)p * 260 + 256 + d] = v;
    g_fcat2[(size_t)p * 132 + 128 + d] = v;
}

// feat [B,256,N] -> g_fcat1[p][c]
__global__ void transpose_feat(const float* __restrict__ feat) {
    __shared__ float tile[32][33];
    int b = blockIdx.z;
    int n0 = blockIdx.x * 32, c0 = blockIdx.y * 32;
    int x = threadIdx.x, y = threadIdx.y;
    tile[y][x] = feat[((size_t)b * 256 + c0 + y) * NPTS + n0 + x];
    __syncthreads();
    g_fcat1[((size_t)(b * NPTS + n0 + y)) * 260 + c0 + x] = tile[x][y];
}

// ---------------- fused point-conv --------------------------------------------
// CTA: 256 threads, 32 points. Chunks of 66 channels (528 f) of agg in smem.
// GEMM: thread = (ptg = tid&15 -> pts {ptg, ptg+16}) x (og = tid>>4 -> o-sets
// {og*4..+3} and {og*4+64..+67}), packed f32x2 accumulators.
template <int CIN, int STRIDE_IN, int OUT_STRIDE>
__global__ void __launch_bounds__(256, 2)
conv_kernel(const float* __restrict__ fcat, const int* __restrict__ knn,
            const float* __restrict__ w_wn, const float* __restrict__ b_wn,
            const float* __restrict__ Lt, const float* __restrict__ b_lin,
            float* __restrict__ out) {
    constexpr int CIN3 = CIN + 3;
    constexpr int ASTRIDE = 532;          // 4*133, 133 odd -> conflict-free LDS
    constexpr int CHUNK_C = 66;           // 528 f per chunk
    constexpr int FBLK = 48;              // Lt staging block

    extern __shared__ float sm[];
    float* s_agg = sm;                    // 32*532
    float* s_w   = sm + 32 * ASTRIDE;     // 32*16*8 = 4096
    float* s_lt  = s_w + 4096;            // 48*128 = 6144

    __shared__ int   s_nbr[32 * 16];
    __shared__ float s_cx[32 * 3];
    __shared__ float s_wn[24];
    __shared__ float s_bwn[8];

    const int tid  = threadIdx.x;
    const int base = blockIdx.x * 32;
    const int boff = (base >> 13) << 13;  // batch offset in point index

    if (tid < 24) s_wn[tid] = w_wn[tid];
    if (tid < 8)  s_bwn[tid] = b_wn[tid];
    if (tid < 96) {
        int pt = tid / 3, d = tid - pt * 3;
        s_cx[pt * 3 + d] = fcat[(size_t)(base + pt) * STRIDE_IN + CIN + d];
    }
    {
        int id = tid;
#pragma unroll
        for (int r = 0; r < 2; ++r, id += 256) {
            int pt = id >> 4, k = id & 15;
            s_nbr[id] = boff + knn[(size_t)(base + pt) * KNN + k];
        }
    }
    __syncthreads();

    // weight-net: w[pt][k][m] = leaky(w_wn @ (xyz_j - xyz_p) + b_wn)
    {
        int id = tid;
#pragma unroll
        for (int r = 0; r < 2; ++r, id += 256) {
            int pt = id >> 4, k = id & 15;
            int j = s_nbr[id];
            const float* nx = fcat + (size_t)j * STRIDE_IN + CIN;
            float px = nx[0] - s_cx[pt * 3 + 0];
            float py = nx[1] - s_cx[pt * 3 + 1];
            float pz = nx[2] - s_cx[pt * 3 + 2];
#pragma unroll
            for (int m = 0; m < 8; ++m) {
                float v = s_wn[m * 3 + 0] * px + s_wn[m * 3 + 1] * py +
                          s_wn[m * 3 + 2] * pz + s_bwn[m];
                s_w[pt * 128 + k * 8 + m] = lrelu(v);
            }
        }
    }
    __syncthreads();

    const int ptg = tid & 15;
    const int og  = tid >> 4;
    const int o0a = og * 4;
    const int o0b = og * 4 + 64;
    const int wid = tid >> 5, lane = tid & 31;

    ull acc[8];
#pragma unroll
    for (int i = 0; i < 8; ++i) acc[i] = 0ULL;

    for (int c0 = 0; c0 < CIN3; c0 += CHUNK_C) {
        const int cc = min(CHUNK_C, CIN3 - c0);

        // ---- agg build: warp wid handles points wid*4 .. wid*4+3
#pragma unroll
        for (int i = 0; i < 4; ++i) {
            const int pt = wid * 4 + i;
            const int* nb = s_nbr + pt * 16;
            const ull* wp = (const ull*)(s_w + pt * 128);
            int nbr_r[16];
#pragma unroll
            for (int k = 0; k < 16; ++k) nbr_r[k] = nb[k];
            for (int cl = lane; cl < cc; cl += 32) {
                const float* fc = fcat + c0 + cl;
                ull a0 = 0, a1 = 0, a2 = 0, a3 = 0;
#pragma unroll
                for (int k = 0; k < 16; ++k) {
                    float fv = __ldg(fc + (size_t)nbr_r[k] * STRIDE_IN);
                    ull fd = dup2(fv);
                    ulonglong2 w01 = *(const ulonglong2*)(wp + k * 4);
                    ulonglong2 w23 = *(const ulonglong2*)(wp + k * 4 + 2);
                    a0 = ffma2(fd, w01.x, a0);
                    a1 = ffma2(fd, w01.y, a1);
                    a2 = ffma2(fd, w23.x, a2);
                    a3 = ffma2(fd, w23.y, a3);
                }
                float* ap = s_agg + pt * ASTRIDE + cl * 8;
                float2 r0 = unpk(a0), r1 = unpk(a1), r2 = unpk(a2), r3 = unpk(a3);
                *(float4*)ap       = make_float4(r0.x, r0.y, r1.x, r1.y);
                *(float4*)(ap + 4) = make_float4(r2.x, r2.y, r3.x, r3.y);
            }
        }
        __syncthreads();

        // ---- GEMM over this chunk's f-range, Lt staged in 48-f blocks
        const int fc_len = cc * 8;
        const float* ltbase = Lt + (size_t)(c0 * 8) * 128;
        const float* aggA = s_agg + ptg * ASTRIDE;
        const float* aggB = s_agg + (ptg + 16) * ASTRIDE;

        for (int fb = 0; fb < fc_len; fb += FBLK) {
            const int blen = min(FBLK, fc_len - fb);
            {
                const float4* src = (const float4*)(ltbase + (size_t)fb * 128);
                float4* dst = (float4*)s_lt;
                const int n4 = blen * 32;
                for (int i = tid; i < n4; i += 256) dst[i] = __ldg(src + i);
            }
            __syncthreads();
            for (int f = 0; f < blen; f += 4) {
                float4 a4 = *(const float4*)(aggA + fb + f);
                float4 b4 = *(const float4*)(aggB + fb + f);
#pragma unroll
                for (int q = 0; q < 4; ++q) {
                    float av = (q == 0) ? a4.x : (q == 1) ? a4.y : (q == 2) ? a4.z : a4.w;
                    float bv = (q == 0) ? b4.x : (q == 1) ? b4.y : (q == 2) ? b4.z : b4.w;
                    ull ad = dup2(av), bd = dup2(bv);
                    const float* ltr = s_lt + (f + q) * 128;
                    ulonglong2 l0 = *(const ulonglong2*)(ltr + o0a);
                    ulonglong2 l1 = *(const ulonglong2*)(ltr + o0b);
                    acc[0] = ffma2(ad, l0.x, acc[0]);
                    acc[1] = ffma2(ad, l0.y, acc[1]);
                    acc[2] = ffma2(ad, l1.x, acc[2]);
                    acc[3] = ffma2(ad, l1.y, acc[3]);
                    acc[4] = ffma2(bd, l0.x, acc[4]);
                    acc[5] = ffma2(bd, l0.y, acc[5]);
                    acc[6] = ffma2(bd, l1.x, acc[6]);
                    acc[7] = ffma2(bd, l1.y, acc[7]);
                }
            }
            __syncthreads();
        }
    }

    // ---- epilogue: bias + leaky, two points, two o-quads each
    float4 bias0 = __ldg((const float4*)(b_lin + o0a));
    float4 bias1 = __ldg((const float4*)(b_lin + o0b));
#pragma unroll
    for (int h = 0; h < 2; ++h) {
        const int p = base + ptg + h * 16;
        float2 t0 = unpk(acc[h * 4 + 0]);
        float2 t1 = unpk(acc[h * 4 + 1]);
        float2 t2 = unpk(acc[h * 4 + 2]);
        float2 t3 = unpk(acc[h * 4 + 3]);
        float4 va = make_float4(lrelu(t0.x + bias0.x), lrelu(t0.y + bias0.y),
                                lrelu(t1.x + bias0.z), lrelu(t1.y + bias0.w));
        float4 vb = make_float4(lrelu(t2.x + bias1.x), lrelu(t2.y + bias1.y),
                                lrelu(t3.x + bias1.z), lrelu(t3.y + bias1.w));
        *(float4*)(out + (size_t)p * OUT_STRIDE + o0a) = va;
        *(float4*)(out + (size_t)p * OUT_STRIDE + o0b) = vb;
    }
}

// ---------------- MLP head -----------------------------------------------------
__global__ void mlp_kernel(const float* __restrict__ w_last, const float* __restrict__ b1,
                           const float* __restrict__ b2, const float* __restrict__ blast,
                           float* __restrict__ out) {
    __shared__ float s_f[16 * 128];
    __shared__ float s_h1[16 * 128];
    __shared__ float s_h2[16 * 64];
    const int tid = threadIdx.x;
    const int p0  = blockIdx.x * 16;

    for (int i = tid; i < 16 * 128; i += 256) s_f[i] = g_f2[(size_t)p0 * 128 + i];
    __syncthreads();

    {
        int o = tid & 127, tg = tid >> 7;
        float acc[8];
#pragma unroll
        for (int i = 0; i < 8; ++i) acc[i] = 0.f;
        for (int c = 0; c < 128; ++c) {
            float wv = g_w1t[c * 128 + o];
#pragma unroll
            for (int i = 0; i < 8; ++i) acc[i] += s_f[(tg * 8 + i) * 128 + c] * wv;
        }
        float bb = b1[o];
#pragma unroll
        for (int i = 0; i < 8; ++i) s_h1[(tg * 8 + i) * 128 + o] = lrelu(acc[i] + bb);
    }
    __syncthreads();

    {
        int jj = tid & 63, tg = tid >> 6;
        float acc[4];
#pragma unroll
        for (int i = 0; i < 4; ++i) acc[i] = 0.f;
        for (int c = 0; c < 128; ++c) {
            float wv = g_w2t[c * 64 + jj];
#pragma unroll
            for (int i = 0; i < 4; ++i) acc[i] += s_h1[(tg * 4 + i) * 128 + c] * wv;
        }
        float bb = b2[jj];
#pragma unroll
        for (int i = 0; i < 4; ++i) s_h2[(tg * 4 + i) * 64 + jj] = lrelu(acc[i] + bb);
    }
    __syncthreads();

    const int b = p0 >> 13, n0 = p0 & (NPTS - 1);
    for (int i = tid; i < 16 * 64; i += 256) {
        int t = i & 15, jj = i >> 4;
        out[((size_t)(b * 64 + jj)) * NPTS + n0 + t] = s_h2[t * 64 + jj];
    }
    if (tid < 48) {
        int t = tid & 15, d = tid >> 4;
        float acc = 0.f;
#pragma unroll 8
        for (int jj = 0; jj < 64; ++jj) acc += w_last[d * 64 + jj] * s_h2[t * 64 + jj];
        out[(size_t)BATCH * 64 * NPTS + ((size_t)(b * 3 + d)) * NPTS + n0 + t] = acc + blast[d];
    }
}

// ---------------- launch --------------------------------------------------------
extern "C" void kernel_launch(void* const* d_in, const int* in_sizes, int n_in,
                              void* d_out, int out_size) {
    const float* xyz    = (const float*)d_in[0];
    const float* feat   = (const float*)d_in[1];
    const int*   knn    = (const int*)d_in[2];
    const float* w_wn1  = (const float*)d_in[3];
    const float* b_wn1  = (const float*)d_in[4];
    const float* w_lin1 = (const float*)d_in[5];
    const float* b_lin1 = (const float*)d_in[6];
    const float* w_wn2  = (const float*)d_in[7];
    const float* b_wn2  = (const float*)d_in[8];
    const float* w_lin2 = (const float*)d_in[9];
    const float* b_lin2 = (const float*)d_in[10];
    const float* w_mlp1 = (const float*)d_in[11];
    const float* b_mlp1 = (const float*)d_in[12];
    const float* w_mlp2 = (const float*)d_in[13];
    const float* b_mlp2 = (const float*)d_in[14];
    const float* w_last = (const float*)d_in[15];
    const float* b_last = (const float*)d_in[16];
    float* out = (float*)d_out;

    void *p_fcat1, *p_fcat2, *p_f2, *p_Lt1, *p_Lt2;
    cudaGetSymbolAddress(&p_fcat1, g_fcat1);
    cudaGetSymbolAddress(&p_fcat2, g_fcat2);
    cudaGetSymbolAddress(&p_f2, g_f2);
    cudaGetSymbolAddress(&p_Lt1, g_Lt1);
    cudaGetSymbolAddress(&p_Lt2, g_Lt2);

    prep_weights<<<(2072 * 128 + 255) / 256, 256>>>(w_lin1, w_lin2, w_mlp1, w_mlp2);
    prep_xyz<<<(NP_TOTAL * 3 + 255) / 256, 256>>>(xyz);
    {
        dim3 tb(32, 32);
        dim3 tg(NPTS / 32, 256 / 32, BATCH);
        transpose_feat<<<tg, tb>>>(feat);
    }

    // dyn smem: (32*532 + 4096 + 48*128) * 4 = 109056 bytes
    const size_t smem = (size_t)(32 * 532 + 4096 + 48 * 128) * 4;

    cudaFuncSetAttribute(conv_kernel<256, 260, 132>,
                         cudaFuncAttributeMaxDynamicSharedMemorySize, (int)smem);
    conv_kernel<256, 260, 132><<<NP_TOTAL / 32, 256, smem>>>(
        (const float*)p_fcat1, knn, w_wn1, b_wn1, (const float*)p_Lt1, b_lin1,
        (float*)p_fcat2);

    cudaFuncSetAttribute(conv_kernel<128, 132, 128>,
                         cudaFuncAttributeMaxDynamicSharedMemorySize, (int)smem);
    conv_kernel<128, 132, 128><<<NP_TOTAL / 32, 256, smem>>>(
        (const float*)p_fcat2, knn, w_wn2, b_wn2, (const float*)p_Lt2, b_lin2,
        (float*)p_f2);

    mlp_kernel<<<NP_TOTAL / 16, 256>>>(w_last, b_mlp1, b_mlp2, b_last, out);
}